// round 5
// baseline (speedup 1.0000x reference)
#include <cuda_runtime.h>
#include <cuda_bf16.h>
#include <math_constants.h>
#include <cstdint>

// Shape (fixed): B=4, S=2048, D=1024, H=16, Dh=64.
#define DM 1024
#define NH 16
#define DH 64
#define BB 4
#define SS 2048
#define MM (BB*SS)        // 8192

// ---------------------------------------------------------------------------
// Scratch (__device__ globals; no allocs allowed).
// ---------------------------------------------------------------------------
__device__ float g_Q [(size_t)MM * DM];
__device__ float g_K [(size_t)MM * DM];
__device__ float g_V [(size_t)MM * DM];
__device__ float g_Ao[(size_t)MM * DM];
__device__ __nv_bfloat16 g_Xh [(size_t)MM * DM];
__device__ __nv_bfloat16 g_Xl [(size_t)MM * DM];
__device__ __nv_bfloat16 g_Aoh[(size_t)MM * DM];
__device__ __nv_bfloat16 g_Aol[(size_t)MM * DM];
__device__ __nv_bfloat16 g_Wh [4][(size_t)DM * DM];
__device__ __nv_bfloat16 g_Wl [4][(size_t)DM * DM];

__device__ __forceinline__ uint32_t smem_u32(const void* p) {
    uint32_t a;
    asm("{ .reg .u64 t; cvta.to.shared.u64 t, %1; cvt.u32.u64 %0, t; }"
        : "=r"(a) : "l"(p));
    return a;
}

// ---- packed f32x2 helpers (sm_100+ family PTX, base-arch) ------------------
__device__ __forceinline__ void lds_v2u64(uint64_t& a, uint64_t& b, uint32_t addr) {
    asm volatile("ld.shared.v2.u64 {%0,%1}, [%2];" : "=l"(a), "=l"(b) : "r"(addr));
}
__device__ __forceinline__ void fma2(uint64_t& d, uint64_t a, uint64_t b) {
    asm volatile("fma.rn.f32x2 %0, %1, %2, %0;" : "+l"(d) : "l"(a), "l"(b));
}
__device__ __forceinline__ void mul2(uint64_t& d, uint64_t a) {
    asm volatile("mul.rn.f32x2 %0, %0, %1;" : "+l"(d) : "l"(a));
}
__device__ __forceinline__ void add2(uint64_t& d, uint64_t a) {
    asm volatile("add.rn.f32x2 %0, %0, %1;" : "+l"(d) : "l"(a));
}
__device__ __forceinline__ uint64_t pack2(float lo, float hi) {
    uint64_t d;
    asm("mov.b64 %0, {%1,%2};" : "=l"(d) : "f"(lo), "f"(hi));
    return d;
}
__device__ __forceinline__ void unpack2(float& lo, float& hi, uint64_t v) {
    asm("mov.b64 {%0,%1}, %2;" : "=f"(lo), "=f"(hi) : "l"(v));
}

// ---------------------------------------------------------------------------
// fp32 -> bf16 hi/lo split (separate buffers), 4 elems/thread.
// ---------------------------------------------------------------------------
__global__ __launch_bounds__(256) void conv_hilo(const float* __restrict__ x,
                                                 __nv_bfloat16* __restrict__ h,
                                                 __nv_bfloat16* __restrict__ l,
                                                 int n) {
    int i = (blockIdx.x * 256 + threadIdx.x) * 4;
    if (i >= n) return;
    float4 v = *(const float4*)(x + i);
    __nv_bfloat16 h0 = __float2bfloat16_rn(v.x);
    __nv_bfloat16 h1 = __float2bfloat16_rn(v.y);
    __nv_bfloat16 h2 = __float2bfloat16_rn(v.z);
    __nv_bfloat16 h3 = __float2bfloat16_rn(v.w);
    __nv_bfloat16 l0 = __float2bfloat16_rn(v.x - __bfloat162float(h0));
    __nv_bfloat16 l1 = __float2bfloat16_rn(v.y - __bfloat162float(h1));
    __nv_bfloat16 l2 = __float2bfloat16_rn(v.z - __bfloat162float(h2));
    __nv_bfloat16 l3 = __float2bfloat16_rn(v.w - __bfloat162float(h3));
    *(__nv_bfloat162*)(h + i)     = __nv_bfloat162(h0, h1);
    *(__nv_bfloat162*)(h + i + 2) = __nv_bfloat162(h2, h3);
    *(__nv_bfloat162*)(l + i)     = __nv_bfloat162(l0, l1);
    *(__nv_bfloat162*)(l + i + 2) = __nv_bfloat162(l2, l3);
}

// ---------------------------------------------------------------------------
// 3-term split GEMM on separate hi/lo tiles, single fp32 accumulator:
//   Y = Ah@Bh^T + Ah@Bl^T + Al@Bh^T   (all bf16 mma.m16n8k16)
// CTA 256x128, BK=32, 4-stage cp.async (192KB), 256 thr, 8 warps of 64x64.
// Per K-chunk: 4 tiles loaded (no Ah duplication) -> 2/3 the traffic of the
// concatenated-K scheme, same MMA count.
// ---------------------------------------------------------------------------
#define BMg 256
#define BNg 128
#define STG 49152            // Ah 16K + Al 16K + Bh 8K + Bl 8K
#define OFF_AL 16384
#define OFF_BH 32768
#define OFF_BL 40960
#define NKg 32               // K=1024 / 32

#define SWCHUNK(row, kc) ((row)*64 + (((kc) ^ (((row)>>1)&3)) << 4))

__device__ __forceinline__ void ldsm_x4(uint32_t* r, uint32_t addr) {
    asm volatile("ldmatrix.sync.aligned.m8n8.x4.shared.b16 {%0,%1,%2,%3}, [%4];"
                 : "=r"(r[0]), "=r"(r[1]), "=r"(r[2]), "=r"(r[3]) : "r"(addr));
}
__device__ __forceinline__ void mma16816(float* c, const uint32_t* a,
                                         uint32_t b0, uint32_t b1) {
    asm volatile("mma.sync.aligned.m16n8k16.row.col.f32.bf16.bf16.f32 "
                 "{%0,%1,%2,%3}, {%4,%5,%6,%7}, {%8,%9}, {%0,%1,%2,%3};"
                 : "+f"(c[0]), "+f"(c[1]), "+f"(c[2]), "+f"(c[3])
                 : "r"(a[0]), "r"(a[1]), "r"(a[2]), "r"(a[3]), "r"(b0), "r"(b1));
}

__device__ __forceinline__ void g_load_stage(uint32_t sbase, int slot, int it,
                                             const char* Ahg, const char* Alg,
                                             const char* Bhg, const char* Blg,
                                             int tid) {
    uint32_t sb = sbase + slot * STG;
    size_t ko = (size_t)it * 64;
#pragma unroll
    for (int j = 0; j < 4; j++) {                 // A tiles: 256 rows
        int id = j * 256 + tid;
        int row = id >> 2, kc = id & 3;
        uint32_t sw = SWCHUNK(row, kc);
        const char* sa = Ahg + (size_t)row * 2048 + ko + kc * 16;
        const char* sl = Alg + (size_t)row * 2048 + ko + kc * 16;
        asm volatile("cp.async.cg.shared.global [%0], [%1], 16;" :: "r"(sb + sw), "l"(sa));
        asm volatile("cp.async.cg.shared.global [%0], [%1], 16;" :: "r"(sb + OFF_AL + sw), "l"(sl));
    }
#pragma unroll
    for (int j = 0; j < 2; j++) {                 // B tiles: 128 rows
        int id = j * 256 + tid;
        int row = id >> 2, kc = id & 3;
        uint32_t sw = SWCHUNK(row, kc);
        const char* sh = Bhg + (size_t)row * 2048 + ko + kc * 16;
        const char* sl = Blg + (size_t)row * 2048 + ko + kc * 16;
        asm volatile("cp.async.cg.shared.global [%0], [%1], 16;" :: "r"(sb + OFF_BH + sw), "l"(sh));
        asm volatile("cp.async.cg.shared.global [%0], [%1], 16;" :: "r"(sb + OFF_BL + sw), "l"(sl));
    }
    asm volatile("cp.async.commit_group;" ::: "memory");
}

__global__ __launch_bounds__(256, 1) void gemm_mma(
    const __nv_bfloat16* __restrict__ Ah, const __nv_bfloat16* __restrict__ Al,
    const __nv_bfloat16* __restrict__ Bh, const __nv_bfloat16* __restrict__ Bl,
    float* __restrict__ Y) {
    extern __shared__ char sm[];
    const uint32_t sbase = smem_u32(sm);
    const int tid = threadIdx.x;
    const int lane = tid & 31;
    const int wid = tid >> 5;
    const int warp_m = wid & 3;       // 4 warp-rows of 64
    const int warp_n = wid >> 2;      // 2 warp-cols of 64
    const int m0 = blockIdx.y * BMg;
    const int n0 = blockIdx.x * BNg;

    const char* Ahg = (const char*)Ah + (size_t)m0 * 2048;
    const char* Alg = (const char*)Al + (size_t)m0 * 2048;
    const char* Bhg = (const char*)Bh + (size_t)n0 * 2048;
    const char* Blg = (const char*)Bl + (size_t)n0 * 2048;

    const int q = lane >> 3, r = lane & 7;

    float c[4][8][4];
#pragma unroll
    for (int mi = 0; mi < 4; mi++)
#pragma unroll
        for (int ni = 0; ni < 8; ni++)
#pragma unroll
            for (int e = 0; e < 4; e++) c[mi][ni][e] = 0.f;

    g_load_stage(sbase, 0, 0, Ahg, Alg, Bhg, Blg, tid);
    g_load_stage(sbase, 1, 1, Ahg, Alg, Bhg, Blg, tid);
    g_load_stage(sbase, 2, 2, Ahg, Alg, Bhg, Blg, tid);

#pragma unroll 1
    for (int i = 0; i < NKg; i++) {
        asm volatile("cp.async.wait_group 2;" ::: "memory");
        __syncthreads();

        if (i + 3 < NKg)
            g_load_stage(sbase, (i + 3) & 3, i + 3, Ahg, Alg, Bhg, Blg, tid);
        else
            asm volatile("cp.async.commit_group;" ::: "memory");

        const uint32_t sb = sbase + (i & 3) * STG;
#pragma unroll
        for (int ks = 0; ks < 2; ks++) {
            const int kc0 = ks * 2;
            const int kca = kc0 + (q >> 1);
            const int kcb = kc0 + (q & 1);

            uint32_t bh[4][4], bl[4][4], a[4][4];
#pragma unroll
            for (int pi = 0; pi < 4; pi++) {
                int rowb = warp_n * 64 + pi * 16 + ((q >> 1) << 3) + r;
                uint32_t sw = SWCHUNK(rowb, kcb);
                ldsm_x4(bh[pi], sb + OFF_BH + sw);
                ldsm_x4(bl[pi], sb + OFF_BL + sw);
            }
#pragma unroll
            for (int mi = 0; mi < 4; mi++) {
                int rowa = warp_m * 64 + mi * 16 + ((q & 1) << 3) + r;
                ldsm_x4(a[mi], sb + SWCHUNK(rowa, kca));
            }
#pragma unroll
            for (int mi = 0; mi < 4; mi++)
#pragma unroll
                for (int ni = 0; ni < 8; ni++)
                    mma16816(c[mi][ni], a[mi],
                             bh[ni >> 1][2 * (ni & 1)], bh[ni >> 1][2 * (ni & 1) + 1]);
#pragma unroll
            for (int mi = 0; mi < 4; mi++)
#pragma unroll
                for (int ni = 0; ni < 8; ni++)
                    mma16816(c[mi][ni], a[mi],
                             bl[ni >> 1][2 * (ni & 1)], bl[ni >> 1][2 * (ni & 1) + 1]);
#pragma unroll
            for (int mi = 0; mi < 4; mi++) {      // reload Al into a regs
                int rowa = warp_m * 64 + mi * 16 + ((q & 1) << 3) + r;
                ldsm_x4(a[mi], sb + OFF_AL + SWCHUNK(rowa, kca));
            }
#pragma unroll
            for (int mi = 0; mi < 4; mi++)
#pragma unroll
                for (int ni = 0; ni < 8; ni++)
                    mma16816(c[mi][ni], a[mi],
                             bh[ni >> 1][2 * (ni & 1)], bh[ni >> 1][2 * (ni & 1) + 1]);
        }
    }

    const int mrow = lane >> 2;
    const int ncol = 2 * (lane & 3);
#pragma unroll
    for (int mi = 0; mi < 4; mi++) {
        int mr = m0 + warp_m * 64 + mi * 16 + mrow;
#pragma unroll
        for (int ni = 0; ni < 8; ni++) {
            int nc = n0 + warp_n * 64 + ni * 8 + ncol;
            *(float2*)(Y + (size_t)mr * DM + nc)       = make_float2(c[mi][ni][0], c[mi][ni][1]);
            *(float2*)(Y + (size_t)(mr + 8) * DM + nc) = make_float2(c[mi][ni][2], c[mi][ni][3]);
        }
    }
}

// ---------------------------------------------------------------------------
// Causal flash attention, fp32 with packed f32x2 math (2x FFMA issue rate).
// Thread pair owns one q-row (32 dims each); hf phases staggered to avoid
// the 2-way LDS bank conflict between the two halves.
// ---------------------------------------------------------------------------
__global__ __launch_bounds__(128) void attn_kernel(const float* __restrict__ Q,
                                                   const float* __restrict__ K,
                                                   const float* __restrict__ V,
                                                   float* __restrict__ O) {
    __shared__ __align__(16) float Ks[64 * 64];
    __shared__ __align__(16) float Vs[64 * 64];

    const int tid = threadIdx.x;
    const int p   = tid >> 1;
    const int hf  = tid & 1;
    const int qt  = blockIdx.x;
    const int h   = blockIdx.y;
    const int b   = blockIdx.z;
    const int qi  = qt * 64 + p;
    const size_t qrow = ((size_t)(b * SS + qi)) * DM + h * DH + hf * 32;
    const unsigned pmask = 3u << ((tid & 31) & ~1);
    const uint32_t kb = smem_u32(Ks) + hf * 128;
    const uint32_t vb = smem_u32(Vs) + hf * 128;

    uint64_t q2[16], acc2[16];
    const float4* qg = (const float4*)(Q + qrow);
#pragma unroll
    for (int i = 0; i < 8; i++) {
        float4 v = qg[i];
        q2[2*i]   = pack2(v.x * 0.125f, v.y * 0.125f);
        q2[2*i+1] = pack2(v.z * 0.125f, v.w * 0.125f);
        acc2[2*i] = 0ull; acc2[2*i+1] = 0ull;
    }
    float mval = -CUDART_INF_F;
    float lval = 0.f;

    for (int t = 0; t <= qt; t++) {
#pragma unroll
        for (int i = 0; i < 8; i++) {
            int fl  = i * 128 + tid;
            int row = fl >> 4, c4 = fl & 15;
            size_t g = ((size_t)(b * SS + t * 64 + row)) * DM + h * DH + c4 * 4;
            *(float4*)&Ks[row * 64 + c4 * 4] = *(const float4*)(K + g);
            *(float4*)&Vs[row * 64 + c4 * 4] = *(const float4*)(V + g);
        }
        __syncthreads();

        const int cmax = (t == qt) ? (p + 1) : 64;
        for (int c = 0; c < cmax; c++) {
            const uint32_t ka = kb + c * 256;
            uint64_t sA = 0ull, sB = 0ull;
#pragma unroll
            for (int j = 0; j < 8; j++) {
                int jj = (j + (hf << 2)) & 7;       // stagger halves (banks)
                uint64_t k0, k1;
                lds_v2u64(k0, k1, ka + jj * 16);
                fma2(sA, q2[2*jj],   k0);
                fma2(sB, q2[2*jj+1], k1);
            }
            add2(sA, sB);
            float lo, hi; unpack2(lo, hi, sA);
            float part = lo + hi;
            float s = part + __shfl_xor_sync(pmask, part, 1);

            if (s > mval) {
                float corr = __expf(mval - s);      // first hit: exp(-inf)=0
                lval *= corr;
                uint64_t c2 = pack2(corr, corr);
#pragma unroll
                for (int i = 0; i < 16; i++) mul2(acc2[i], c2);
                mval = s;
            }
            float pe = __expf(s - mval);
            lval += pe;
            uint64_t p2 = pack2(pe, pe);

            const uint32_t va = vb + c * 256;
#pragma unroll
            for (int j = 0; j < 8; j++) {
                int jj = (j + (hf << 2)) & 7;
                uint64_t v0, v1;
                lds_v2u64(v0, v1, va + jj * 16);
                fma2(acc2[2*jj],   p2, v0);
                fma2(acc2[2*jj+1], p2, v1);
            }
        }
        __syncthreads();
    }

    const float inv = 1.0f / lval;
    float4* og = (float4*)(O + qrow);
#pragma unroll
    for (int i = 0; i < 8; i++) {
        float a, bq, cc, d;
        unpack2(a, bq, acc2[2*i]);
        unpack2(cc, d, acc2[2*i+1]);
        og[i] = make_float4(a * inv, bq * inv, cc * inv, d * inv);
    }
}

// ---------------------------------------------------------------------------
// Launch.
// ---------------------------------------------------------------------------
extern "C" void kernel_launch(void* const* d_in, const int* in_sizes, int n_in,
                              void* d_out, int out_size) {
    const float* X  = (const float*)d_in[0];
    const float* W[4] = { (const float*)d_in[1], (const float*)d_in[2],
                          (const float*)d_in[3], (const float*)d_in[4] };
    float* out = (float*)d_out;

    void *pq, *pk, *pv, *po, *pxh, *pxl, *paoh, *paol, *pwh, *pwl;
    cudaGetSymbolAddress(&pq,  g_Q);   cudaGetSymbolAddress(&pk,  g_K);
    cudaGetSymbolAddress(&pv,  g_V);   cudaGetSymbolAddress(&po,  g_Ao);
    cudaGetSymbolAddress(&pxh, g_Xh);  cudaGetSymbolAddress(&pxl, g_Xl);
    cudaGetSymbolAddress(&paoh, g_Aoh); cudaGetSymbolAddress(&paol, g_Aol);
    cudaGetSymbolAddress(&pwh, g_Wh);  cudaGetSymbolAddress(&pwl, g_Wl);

    __nv_bfloat16* Xh  = (__nv_bfloat16*)pxh;
    __nv_bfloat16* Xl  = (__nv_bfloat16*)pxl;
    __nv_bfloat16* Aoh = (__nv_bfloat16*)paoh;
    __nv_bfloat16* Aol = (__nv_bfloat16*)paol;
    __nv_bfloat16* Wh  = (__nv_bfloat16*)pwh;   // [4][DM*DM]
    __nv_bfloat16* Wl  = (__nv_bfloat16*)pwl;

    cudaFuncSetAttribute(gemm_mma, cudaFuncAttributeMaxDynamicSharedMemorySize,
                         4 * STG);

    const int nX = MM * DM;
    const int nW = DM * DM;
    const size_t ws = (size_t)nW;

    conv_hilo<<<nX / 1024, 256>>>(X, Xh, Xl, nX);
    for (int w = 0; w < 4; w++)
        conv_hilo<<<nW / 1024, 256>>>(W[w], Wh + w * ws, Wl + w * ws, nW);

    dim3 gg(DM / BNg, MM / BMg);   // (8, 32)
    gemm_mma<<<gg, 256, 4 * STG>>>(Xh, Xl, Wh + 0 * ws, Wl + 0 * ws, (float*)pq);
    gemm_mma<<<gg, 256, 4 * STG>>>(Xh, Xl, Wh + 1 * ws, Wl + 1 * ws, (float*)pk);
    gemm_mma<<<gg, 256, 4 * STG>>>(Xh, Xl, Wh + 2 * ws, Wl + 2 * ws, (float*)pv);

    dim3 ga(SS / 64, NH, BB);      // (32, 16, 4)
    attn_kernel<<<ga, 128>>>((const float*)pq, (const float*)pk,
                             (const float*)pv, (float*)po);

    conv_hilo<<<nX / 1024, 256>>>((const float*)po, Aoh, Aol, nX);
    gemm_mma<<<gg, 256, 4 * STG>>>(Aoh, Aol, Wh + 3 * ws, Wl + 3 * ws, out);
}